// round 4
// baseline (speedup 1.0000x reference)
#include <cuda_runtime.h>

// Scratch for per-row scores: s_i (includes +bias) and s_j.
__device__ float g_si[65536];
__device__ float g_sj[65536];

// ---------------------------------------------------------------------------
// Kernel 1 (primary): per-row dual dot product (warp per row).
// ---------------------------------------------------------------------------
__global__ void row_scores_kernel(const float4* __restrict__ x4,
                                  const float4* __restrict__ W4,
                                  const float* __restrict__ bptr,
                                  int n_rows, int d4 /* = D/4 = 32 */)
{
    asm volatile("griddepcontrol.launch_dependents;" ::: "memory");

    int warp_id = (blockIdx.x * blockDim.x + threadIdx.x) >> 5;
    int lane = threadIdx.x & 31;
    if (warp_id >= n_rows) return;

    float s1 = 0.f, s2 = 0.f;
    if (lane < d4) {
        float4 xv = __ldg(x4 + warp_id * d4 + lane);
        float4 w1 = __ldg(W4 + lane);        // W[0:D]
        float4 w2 = __ldg(W4 + d4 + lane);   // W[D:2D]
        s1 = xv.x * w1.x + xv.y * w1.y + xv.z * w1.z + xv.w * w1.w;
        s2 = xv.x * w2.x + xv.y * w2.y + xv.z * w2.z + xv.w * w2.w;
    }
    #pragma unroll
    for (int off = 16; off > 0; off >>= 1) {
        s1 += __shfl_down_sync(0xFFFFFFFFu, s1, off);
        s2 += __shfl_down_sync(0xFFFFFFFFu, s2, off);
    }
    if (lane == 0) {
        g_si[warp_id] = s1 + *bptr;  // fold bias into si
        g_sj[warp_id] = s2;
    }
}

// ---------------------------------------------------------------------------
// Kernel 2 (secondary): fused elementwise pass.
//   out = 0.4*tanh((si+sj)/2) + 0.4 + 0.2*adj     [== 0.8*sigmoid + 0.2*adj]
// 8 float4 per thread, all 8 adj loads front-batched (MLP=8) before the
// griddepcontrol.wait.
// ---------------------------------------------------------------------------
#define VEC 8

__device__ __forceinline__ float sigterm(float z, float a)
{
    float t;
    asm("tanh.approx.f32 %0, %1;" : "=f"(t) : "f"(z * 0.5f));
    return fmaf(0.4f, t, fmaf(0.2f, a, 0.4f));
}

__device__ __forceinline__ float4 sigfuse(float si, float4 sj, float4 a)
{
    float4 r;
    r.x = sigterm(si + sj.x, a.x);
    r.y = sigterm(si + sj.y, a.y);
    r.z = sigterm(si + sj.z, a.z);
    r.w = sigterm(si + sj.w, a.w);
    return r;
}

__global__ void __launch_bounds__(256)
fuse_kernel(const float4* __restrict__ adj4,
            float4* __restrict__ out4,
            int total4, int log2_n4, int log2_n)
{
    const float4* __restrict__ sj4 = reinterpret_cast<const float4*>(g_sj);
    int base = blockIdx.x * (256 * VEC) + threadIdx.x;

    if (base + (VEC - 1) * 256 < total4) {
        // Front-batch all 8 adj loads: independent DRAM traffic in flight
        // before the PDL wait and before any consumer.
        float4 a[VEC];
        #pragma unroll
        for (int k = 0; k < VEC; k++)
            a[k] = __ldcs(adj4 + base + k * 256);

        asm volatile("griddepcontrol.wait;" ::: "memory");

        int mask = (1 << log2_n4) - 1;
        #pragma unroll
        for (int k = 0; k < VEC; k++) {
            int e = base + k * 256;
            int row = e >> log2_n4;
            float si = __ldg(g_si + row);
            float4 sj = __ldg(sj4 + ((row >> log2_n) << log2_n4) + (e & mask));
            __stcs(out4 + e, sigfuse(si, sj, a[k]));
        }
    } else {
        asm volatile("griddepcontrol.wait;" ::: "memory");
        int mask = (1 << log2_n4) - 1;
        #pragma unroll
        for (int k = 0; k < VEC; k++) {
            int e = base + k * 256;
            if (e < total4) {
                float4 a = __ldcs(adj4 + e);
                int row = e >> log2_n4;
                float si = __ldg(g_si + row);
                float4 sj = __ldg(sj4 + ((row >> log2_n) << log2_n4) + (e & mask));
                __stcs(out4 + e, sigfuse(si, sj, a));
            }
        }
    }
}

extern "C" void kernel_launch(void* const* d_in, const int* in_sizes, int n_in,
                              void* d_out, int out_size)
{
    const float* x   = (const float*)d_in[0];   // [B, N, D]
    const float* adj = (const float*)d_in[1];   // [B, N, N]
    const float* W   = (const float*)d_in[2];   // [2D]
    const float* b   = (const float*)d_in[3];   // scalar

    const int D = 128;
    int n_rows = in_sizes[0] / D;               // B*N = 16384
    long long N_ll = (long long)in_sizes[1] * D / in_sizes[0];
    int N = (int)N_ll;                           // 2048
    int log2_n = 0; while ((1 << log2_n) < N) log2_n++;
    int log2_n4 = log2_n - 2;

    // Kernel 1 (primary).
    {
        int warps_per_block = 8;
        int blocks = (n_rows + warps_per_block - 1) / warps_per_block;
        row_scores_kernel<<<blocks, 256>>>(
            (const float4*)x, (const float4*)W, b, n_rows, D / 4);
    }

    // Kernel 2 (secondary) with programmatic dependent launch.
    {
        int total4 = out_size / 4;               // 8.39M
        int per_block = 256 * VEC;
        int blocks = (total4 + per_block - 1) / per_block;

        cudaLaunchAttribute attrs[1];
        attrs[0].id = cudaLaunchAttributeProgrammaticStreamSerialization;
        attrs[0].val.programmaticStreamSerializationAllowed = 1;

        cudaLaunchConfig_t cfg = {};
        cfg.gridDim = dim3((unsigned)blocks, 1, 1);
        cfg.blockDim = dim3(256, 1, 1);
        cfg.dynamicSmemBytes = 0;
        cfg.stream = 0;
        cfg.attrs = attrs;
        cfg.numAttrs = 1;

        cudaError_t err = cudaLaunchKernelEx(&cfg, fuse_kernel,
            (const float4*)adj, (float4*)d_out, total4, log2_n4, log2_n);
        if (err != cudaSuccess) {
            cudaGetLastError();
            fuse_kernel<<<blocks, 256>>>(
                (const float4*)adj, (float4*)d_out, total4, log2_n4, log2_n);
        }
    }
}